// round 10
// baseline (speedup 1.0000x reference)
#include <cuda_runtime.h>
#include <cuda_pipeline.h>
#include <math.h>

#define NC 23
#define NG 20000
#define NN 64
#define NH 64

#define BLKA 128
#define NBLKA ((NG + BLKA - 1) / BLKA)   // 157

#define SEGS 4
#define BLK 256
#define WARPS (BLK / 32)
#define STREAMS (WARPS * 2)              // 16 half-warp streams per block
#define DEPTH 8                          // cp.async ring depth per stream

// ---- scratch (static device globals; no allocation in kernel_launch) ----
__device__ int   d_offset[NC + 1];
__device__ int   d_blockhist[NBLKA * NC];
__device__ int   d_assign[NG];
__device__ int   d_pack[NG];             // gene idx, bucketed by chromosome
__device__ float d_outacc[NN * NC * NH];
__device__ float d_sumw[NN * NC];

// ---------------- P1: per-gene assignment + per-block hist + zeroing -------

__global__ __launch_bounds__(BLKA)
void k_assign(const float* __restrict__ chrom) {
    __shared__ int s_hist[NC];
    const int tid = threadIdx.x;
    const int g = blockIdx.x * BLKA + tid;

    if (tid < NC) s_hist[tid] = 0;
    __syncthreads();

    if (g < NG) {
        int ci = 0;
        #pragma unroll
        for (int c = 0; c < NC; c++) {
            float v = chrom[c * NG + g];       // coalesced across g
            if (v != 0.f) ci = c;              // one-hot: exactly one hit
        }
        d_assign[g] = ci;
        atomicAdd(&s_hist[ci], 1);             // smem only
    }

    // fold accumulator zeroing in
    const int nt = NBLKA * BLKA;
    const int gt = blockIdx.x * BLKA + tid;
    for (int i = gt; i < NN * NC * NH; i += nt)
        d_outacc[i] = 0.f;
    if (gt < NN * NC)
        d_sumw[gt] = 0.f;

    __syncthreads();
    if (tid < NC) d_blockhist[blockIdx.x * NC + tid] = s_hist[tid];
}

// ---------------- P2: scatter; each block derives offsets locally ----------

__global__ __launch_bounds__(BLKA)
void k_scatter() {
    __shared__ int s_off[NC];
    __shared__ int s_base[NC];
    const int tid = threadIdx.x;
    const int bid = blockIdx.x;
    const int g = bid * BLKA + tid;

    int tot = 0, pre = 0;
    if (tid < NC) {
        #pragma unroll 4
        for (int b = 0; b < NBLKA; b++) {
            int h = d_blockhist[b * NC + tid];
            tot += h;
            if (b < bid) pre += h;
        }
    }
    if (tid < 32) {
        int v = (tid < NC) ? tot : 0;
        int acc = v;
        #pragma unroll
        for (int d = 1; d < 32; d <<= 1) {
            int u = __shfl_up_sync(0xffffffffu, acc, d);
            if (tid >= d) acc += u;
        }
        if (tid < NC) {
            s_off[tid] = acc - v;
            if (bid == 0) {
                d_offset[tid] = acc - v;
                if (tid == NC - 1) d_offset[NC] = acc;
            }
        }
    }
    __syncthreads();
    if (tid < NC) s_base[tid] = s_off[tid] + pre;
    __syncthreads();

    if (g < NG) {
        int ci = d_assign[g];
        int pos = atomicAdd(&s_base[ci], 1);   // smem-only cursor
        d_pack[pos] = g;
    }
}

// ---------------- main fused pass -------------------------------------------
// grid: (SEGS, NC, NN). Each half-warp streams genes; x rows arrive via a
// DEPTH-deep cp.async ring in smem, fully decoupling DRAM latency from the
// dot/shfl/exp compute chain.

__device__ __forceinline__ void compute_gene(
    const float4 xv, const float4 a4,
    unsigned hm, float4& acc, float& sumw)
{
    float s = a4.x * xv.x + a4.y * xv.y + a4.z * xv.z + a4.w * xv.w;
    s += __shfl_xor_sync(hm, s, 8);
    s += __shfl_xor_sync(hm, s, 4);
    s += __shfl_xor_sync(hm, s, 2);
    s += __shfl_xor_sync(hm, s, 1);
    float w = 0.f;
    if (s != 0.f) {
        float lr = s > 0.f ? s : 0.2f * s;   // leaky_relu(0.2)
        w = __expf(lr);
    }
    acc.x += w * xv.x;
    acc.y += w * xv.y;
    acc.z += w * xv.z;
    acc.w += w * xv.w;
    sumw += w;
}

__global__ __launch_bounds__(BLK)
void k_main(const float* __restrict__ x, const float* __restrict__ attn) {
    const int seg = blockIdx.x;
    const int ci  = blockIdx.y;
    const int n   = blockIdx.z;

    const int bstart = d_offset[ci];
    const int bend   = d_offset[ci + 1];
    const int cnt    = bend - bstart;
    const int s0 = bstart + (int)((long long)cnt * seg / SEGS);
    const int s1 = bstart + (int)((long long)cnt * (seg + 1) / SEGS);

    const int tid  = threadIdx.x;
    const int wid  = tid >> 5;
    const int lane = tid & 31;
    const int hl   = lane & 15;   // lane within half-warp
    const int half = lane >> 4;
    const unsigned hm = half ? 0xffff0000u : 0x0000ffffu;

    const float4 a4 =
        *reinterpret_cast<const float4*>(attn + ci * NH + hl * 4);

    const float* xbase = x + (long long)n * NG * NH;

    float4 acc = make_float4(0.f, 0.f, 0.f, 0.f);
    float sumw = 0.f;

    const int stream = wid * 2 + half;
    const int step   = STREAMS;          // 16

    // cp.async ring: [stream][slot][hl] of float4
    __shared__ float4 s_buf[STREAMS * DEPTH * 16];
    float4* mybuf = &s_buf[stream * DEPTH * 16 + hl];

    int pl = s0 + stream;   // load cursor
    int pc = s0 + stream;   // consume cursor

    // prologue: commit exactly DEPTH groups (empty if out of genes)
    #pragma unroll
    for (int d = 0; d < DEPTH; d++) {
        if (pl < s1) {
            const int g = d_pack[pl];
            __pipeline_memcpy_async(&mybuf[d * 16],
                                    xbase + (long long)g * NH + hl * 4, 16);
        }
        __pipeline_commit();
        pl += step;
    }

    // steady state: one group consumed + one group committed per iteration
    int slot = 0;
    while (pc < s1) {
        __pipeline_wait_prior(DEPTH - 1);     // slot's group complete
        const float4 xv = mybuf[slot * 16];
        if (pl < s1) {
            const int g = d_pack[pl];
            __pipeline_memcpy_async(&mybuf[slot * 16],
                                    xbase + (long long)g * NH + hl * 4, 16);
        }
        __pipeline_commit();
        pl += step;

        compute_gene(xv, a4, hm, acc, sumw);

        pc += step;
        slot = (slot + 1) & (DEPTH - 1);
    }

    // combine halves: lanes 0..15 pick up lanes 16..31
    acc.x += __shfl_down_sync(0xffffffffu, acc.x, 16);
    acc.y += __shfl_down_sync(0xffffffffu, acc.y, 16);
    acc.z += __shfl_down_sync(0xffffffffu, acc.z, 16);
    acc.w += __shfl_down_sync(0xffffffffu, acc.w, 16);
    sumw  += __shfl_down_sync(0xffffffffu, sumw, 16);

    // block-level reduction in smem
    __shared__ float s_acc[NH];
    __shared__ float s_sum;
    if (tid < NH) s_acc[tid] = 0.f;
    if (tid == 0) s_sum = 0.f;
    __syncthreads();

    if (lane < 16) {
        atomicAdd(&s_acc[hl * 4 + 0], acc.x);
        atomicAdd(&s_acc[hl * 4 + 1], acc.y);
        atomicAdd(&s_acc[hl * 4 + 2], acc.z);
        atomicAdd(&s_acc[hl * 4 + 3], acc.w);
    }
    if (lane == 0) atomicAdd(&s_sum, sumw);
    __syncthreads();

    const int slot_out = n * NC + ci;
    float* oacc = d_outacc + (long long)slot_out * NH;
    if (tid < NH) atomicAdd(&oacc[tid], s_acc[tid]);
    if (tid == 0) atomicAdd(&d_sumw[slot_out], s_sum);
}

// ---------------- epilogue --------------------------------------------------

__global__ void k_final(float4* __restrict__ out) {
    int t = blockIdx.x * blockDim.x + threadIdx.x;   // float4 index
    if (t < NN * NC * NH / 4) {
        int ni = t / (NH / 4);
        float s = fmaxf(d_sumw[ni], 1e-10f);
        float4 v = reinterpret_cast<const float4*>(d_outacc)[t];
        v.x /= s; v.y /= s; v.z /= s; v.w /= s;
        out[t] = v;
    }
}

// ---------------- launcher --------------------------------------------------

extern "C" void kernel_launch(void* const* d_in, const int* in_sizes, int n_in,
                              void* d_out, int out_size) {
    const float* x     = (const float*)d_in[0];   // (N, G, H)
    const float* chrom = (const float*)d_in[1];   // (C, G)
    const float* attn  = (const float*)d_in[2];   // (C, H)
    float4* out = (float4*)d_out;                 // (N, C, H)

    (void)in_sizes; (void)n_in; (void)out_size;

    // bucket genes by chromosome (contention-free counting sort) + zero accum
    k_assign<<<NBLKA, BLKA>>>(chrom);
    k_scatter<<<NBLKA, BLKA>>>();

    // fused attention + weighted accumulation (cp.async-decoupled streaming)
    dim3 grid(SEGS, NC, NN);
    k_main<<<grid, BLK>>>(x, attn);

    // normalize
    const int nf4 = NN * NC * NH / 4;
    k_final<<<(nf4 + BLK - 1) / BLK, BLK>>>(out);
}